// round 6
// baseline (speedup 1.0000x reference)
#include <cuda_runtime.h>

// ---------------------------------------------------------------------------
// RelationOnSpatial, algebraically collapsed:
//   f = softmax(s_theta[:,None]+s_phi[None,:],axis=1) == softmax(s_phi)
//   (theta path dead, all output rows identical; constant bias cancels).
//   z[i,c] = gamma * ( g_w[c,:,:] . q / S + g_b[c] )
//   q[cy,ky,kx] = sum_{h,w} y[cy,h,w] * e[h+1-ky, w+1-kx],  e=exp(s_phi), S=sum e
// ---------------------------------------------------------------------------

#define CY   256
#define H    128
#define WW   128
#define HW   16384
#define KEL  2304            // CY*9

__device__ float d_phi_part[32 * KEL];                // kA partials (32 chunks)
__device__ __align__(16) float d_sphi_part[64 * HW];  // conv partials (64 slots)
__device__ __align__(16) float d_e[HW];
__device__ float d_Spart[64];
__device__ float d_qe_w[32 * KEL];                    // per-strip q partials
__device__ __align__(16) float d_q[KEL];
__device__ __align__(16) float d_r[256];

// ---------------------------------------------------------------------------
// A: phi_eff partials over 32 chunks of 8 input channels.  grid (9,32) x 256.
// ---------------------------------------------------------------------------
__global__ void kA(const float* __restrict__ phi_w,
                   const float* __restrict__ concat_w) {
    const int t   = threadIdx.x;
    const int out = blockIdx.x * 256 + t;
    const int p   = blockIdx.y;
    const float* wp = concat_w + 256;
    float s = 0.f;
    #pragma unroll
    for (int c = p * 8; c < p * 8 + 8; ++c)
        s += wp[c] * phi_w[c * KEL + out];
    d_phi_part[p * KEL + out] = s;
}

// ---------------------------------------------------------------------------
// B: 256ch -> 1ch 3x3 conv partials, halo via shfl.
// grid (16 strips of 8 rows, 64 chunks of 4 ch) x 256. Warp w = row strip*8+w.
// ---------------------------------------------------------------------------
__global__ void kB(const float* __restrict__ y) {
    __shared__ float kk[36];
    const int t = threadIdx.x;
    const int strip = blockIdx.x, chunk = blockIdx.y;

    if (t < 36) {
        float s = 0.f;
        #pragma unroll
        for (int p = 0; p < 32; ++p) s += d_phi_part[p * KEL + chunk * 36 + t];
        kk[t] = s;
    }
    __syncthreads();

    const int w = t >> 5, g = t & 31;
    const int r = strip * 8 + w;
    const bool up = (r > 0), dn = (r < H - 1);
    const float4 Z = make_float4(0.f, 0.f, 0.f, 0.f);
    float4 acc = Z;

    #pragma unroll
    for (int ci = 0; ci < 4; ++ci) {
        const int cy = chunk * 4 + ci;
        const float* base = y + cy * HW + r * WW + 4 * g;
        float4 row[3];
        row[0] = up ? *(const float4*)(base - WW) : Z;
        row[1] = *(const float4*)base;
        row[2] = dn ? *(const float4*)(base + WW) : Z;

        #pragma unroll
        for (int ky = 0; ky < 3; ++ky) {
            const float4 V = row[ky];
            float L = __shfl_up_sync(~0u, V.w, 1);   if (g == 0)  L = 0.f;
            float R = __shfl_down_sync(~0u, V.x, 1); if (g == 31) R = 0.f;
            const float k0 = kk[ci * 9 + ky * 3 + 0];
            const float k1 = kk[ci * 9 + ky * 3 + 1];
            const float k2 = kk[ci * 9 + ky * 3 + 2];
            acc.x += k0 * L   + k1 * V.x + k2 * V.y;
            acc.y += k0 * V.x + k1 * V.y + k2 * V.z;
            acc.z += k0 * V.y + k1 * V.z + k2 * V.w;
            acc.w += k0 * V.z + k1 * V.w + k2 * R;
        }
    }
    *(float4*)&d_sphi_part[chunk * HW + r * WW + 4 * g] = acc;
}

// ---------------------------------------------------------------------------
// C: e = exp(sum of 64 chunk partials); per-block S partials. grid 64 x 256.
// ---------------------------------------------------------------------------
__global__ void kC() {
    __shared__ float red[8];
    const int t = threadIdx.x;
    const int idx = blockIdx.x * 256 + t;
    float s = 0.f;
    #pragma unroll
    for (int p = 0; p < 64; ++p) s += d_sphi_part[p * HW + idx];
    float e = __expf(s);
    d_e[idx] = e;
    float v = e;
    #pragma unroll
    for (int o = 16; o; o >>= 1) v += __shfl_xor_sync(~0u, v, o);
    if ((t & 31) == 0) red[t >> 5] = v;
    __syncthreads();
    if (t == 0) {
        float tot = 0.f;
        #pragma unroll
        for (int i = 0; i < 8; ++i) tot += red[i];
        d_Spart[blockIdx.x] = tot;
    }
}

// ---------------------------------------------------------------------------
// D: q partials. grid (32 strips of 4 rows, 32 channel-octets) x 256.
// Warp w owns channel oct*8+w over the 4-row strip. 4 y-rows preloaded,
// e-window slides in registers, one 9-value butterfly per warp.
// ---------------------------------------------------------------------------
__global__ void kD(const float* __restrict__ y) {
    __shared__ __align__(16) float sm[6 * 132];
    __shared__ float redsm[72];
    const int t = threadIdx.x;
    const int strip = blockIdx.x;   // 0..31
    const int oct   = blockIdx.y;   // 0..31
    const int h0 = strip * 4;

    // e-tile rows 0..5 = global rows h0-1..h0+4, cols 0..131 = global -1..130
    for (int i = t; i < 6 * 132; i += 256) {
        const int rr = i / 132, cc = i - rr * 132;
        const int gr = h0 - 1 + rr, gc = cc - 1;
        float v = 0.f;
        if (gr >= 0 && gr < H && gc >= 0 && gc < WW) v = d_e[gr * WW + gc];
        sm[i] = v;
    }
    __syncthreads();

    const int w = t >> 5, g = t & 31;
    const int cy = oct * 8 + w;
    const float* yb = y + cy * HW + h0 * WW + 4 * g;

    float4 yv[4];
    #pragma unroll
    for (int j = 0; j < 4; ++j) yv[j] = *(const float4*)(yb + j * WW);

    float a[9];
    #pragma unroll
    for (int k = 0; k < 9; ++k) a[k] = 0.f;

    float4 E0[3]; float2 E1[3];
    #pragma unroll
    for (int j = 0; j < 3; ++j) {
        const float* bp = &sm[j * 132 + 4 * g];
        E0[j] = *(const float4*)bp;
        E1[j] = *(const float2*)(bp + 4);
    }

    #pragma unroll
    for (int j = 0; j < 4; ++j) {
        #pragma unroll
        for (int ww = 0; ww < 3; ++ww) {
            const int ky = 2 - ww;
            a[3*ky+2] += yv[j].x*E0[ww].x + yv[j].y*E0[ww].y + yv[j].z*E0[ww].z + yv[j].w*E0[ww].w;
            a[3*ky+1] += yv[j].x*E0[ww].y + yv[j].y*E0[ww].z + yv[j].z*E0[ww].w + yv[j].w*E1[ww].x;
            a[3*ky+0] += yv[j].x*E0[ww].z + yv[j].y*E0[ww].w + yv[j].z*E1[ww].x + yv[j].w*E1[ww].y;
        }
        if (j < 3) {
            E0[0] = E0[1]; E1[0] = E1[1];
            E0[1] = E0[2]; E1[1] = E1[2];
            const float* bp = &sm[(j + 3) * 132 + 4 * g];
            E0[2] = *(const float4*)bp;
            E1[2] = *(const float2*)(bp + 4);
        }
    }

    #pragma unroll
    for (int k = 0; k < 9; ++k)
        #pragma unroll
        for (int o = 16; o; o >>= 1)
            a[k] += __shfl_xor_sync(~0u, a[k], o);

    if (g == 0) {
        #pragma unroll
        for (int k = 0; k < 9; ++k) redsm[w * 9 + k] = a[k];
    }
    __syncthreads();
    if (t < 72) {
        const int ch = t / 9, k = t - ch * 9;
        d_qe_w[strip * KEL + (oct * 8 + ch) * 9 + k] = redsm[t];
    }
}

// ---------------------------------------------------------------------------
// E0: q[j] = sum over 32 strips.  grid 9 x 256.
// ---------------------------------------------------------------------------
__global__ void kE0() {
    const int j = blockIdx.x * 256 + threadIdx.x;
    float s = 0.f;
    #pragma unroll
    for (int sb = 0; sb < 32; ++sb) s += d_qe_w[sb * KEL + j];
    d_q[j] = s;
}

// ---------------------------------------------------------------------------
// E: r[c] = gamma*(g_w[c,:].q / S + g_b[c]).  256 blocks x 256.
// ---------------------------------------------------------------------------
__global__ void kE(const float* __restrict__ g_w,
                   const float* __restrict__ g_b,
                   const float* __restrict__ gamma) {
    __shared__ float red[256];
    const int c = blockIdx.x, t = threadIdx.x;
    const float4* gw4 = (const float4*)(g_w + c * KEL);
    const float4* q4  = (const float4*)d_q;
    float s = 0.f;
    for (int j = t; j < 576; j += 256) {
        const float4 gv = gw4[j];
        const float4 qv = q4[j];
        s += gv.x * qv.x + gv.y * qv.y + gv.z * qv.z + gv.w * qv.w;
    }
    red[t] = s;
    __syncthreads();
    for (int o = 128; o > 0; o >>= 1) {
        if (t < o) red[t] += red[t + o];
        __syncthreads();
    }
    if (t == 0) {
        float S = 0.f;
        #pragma unroll
        for (int i = 0; i < 64; ++i) S += d_Spart[i];
        d_r[c] = gamma[0] * (red[0] / S + g_b[c]);
    }
}

// ---------------------------------------------------------------------------
// F: broadcast r to 1024 rows, float4.  256 x 256.
// ---------------------------------------------------------------------------
__global__ void kF(float* __restrict__ out) {
    const int i = blockIdx.x * 256 + threadIdx.x;
    ((float4*)out)[i] = ((const float4*)d_r)[i & 63];
}

extern "C" void kernel_launch(void* const* d_in, const int* in_sizes, int n_in,
                              void* d_out, int out_size) {
    // order: x, y, g_w, g_b, phi_w, phi_b, theta_w, theta_b, concat_w, gamma
    const float* y        = (const float*)d_in[1];
    const float* g_w      = (const float*)d_in[2];
    const float* g_b      = (const float*)d_in[3];
    const float* phi_w    = (const float*)d_in[4];
    const float* concat_w = (const float*)d_in[8];
    const float* gamma    = (const float*)d_in[9];

    kA<<<dim3(9, 32), 256>>>(phi_w, concat_w);
    kB<<<dim3(16, 64), 256>>>(y);
    kC<<<64, 256>>>();
    kD<<<dim3(32, 32), 256>>>(y);
    kE0<<<9, 256>>>();
    kE<<<256, 256>>>(g_w, g_b, gamma);
    kF<<<256, 256>>>((float*)d_out);
}

// round 7
// speedup vs baseline: 1.0760x; 1.0760x over previous
#include <cuda_runtime.h>

// ---------------------------------------------------------------------------
// RelationOnSpatial, algebraically collapsed:
//   f = softmax(s_theta[:,None]+s_phi[None,:],axis=1) == softmax(s_phi)
//   (theta path dead, all output rows identical; constant bias cancels).
//   z[i,c] = gamma * ( g_w[c,:,:] . q / S + g_b[c] )
//   q[cy,ky,kx] = sum_{h,w} y[cy,h,w] * e[h+1-ky, w+1-kx],  e=exp(s_phi), S=sum e
// ---------------------------------------------------------------------------

#define CY   256
#define H    128
#define WW   128
#define HW   16384
#define KEL  2304            // CY*9

__device__ float d_phi_part[32 * KEL];                // kA partials (32 chunks)
__device__ __align__(16) float d_sphi_part[32 * HW];  // conv partials per chunk
__device__ __align__(16) float d_e[HW];
__device__ float d_Spart[16];
__device__ float d_qe_w[16 * KEL];                    // per-strip q partials
__device__ __align__(16) float d_q[KEL];
__device__ __align__(16) float d_r[256];

// ---------------------------------------------------------------------------
// A: phi_eff partials over 32 chunks of 8 output channels.  grid (9,32) x 256.
// ---------------------------------------------------------------------------
__global__ void kA(const float* __restrict__ phi_w,
                   const float* __restrict__ concat_w) {
    const int t   = threadIdx.x;
    const int out = blockIdx.x * 256 + t;
    const int p   = blockIdx.y;
    const float* wp = concat_w + 256;
    float s = 0.f;
    #pragma unroll
    for (int c = p * 8; c < p * 8 + 8; ++c)
        s += wp[c] * phi_w[c * KEL + out];
    d_phi_part[p * KEL + out] = s;
}

// ---------------------------------------------------------------------------
// B: 256ch -> 1ch 3x3 conv partials, halo via shfl.
// grid (16 strips, 32 chunks of 8 ch) x 256.  Warp w owns row strip*8+w.
// ---------------------------------------------------------------------------
__global__ void kB(const float* __restrict__ y) {
    __shared__ float kk[72];
    const int t = threadIdx.x;
    const int strip = blockIdx.x, chunk = blockIdx.y;

    if (t < 72) {
        float s = 0.f;
        #pragma unroll
        for (int p = 0; p < 32; ++p) s += d_phi_part[p * KEL + chunk * 72 + t];
        kk[t] = s;
    }
    __syncthreads();

    const int w = t >> 5, g = t & 31;
    const int r = strip * 8 + w;
    const bool up = (r > 0), dn = (r < H - 1);
    const float4 Z = make_float4(0.f, 0.f, 0.f, 0.f);
    float4 acc = Z;

    #pragma unroll 4
    for (int ci = 0; ci < 8; ++ci) {
        const int cy = chunk * 8 + ci;
        const float* base = y + cy * HW + r * WW + 4 * g;
        float4 row[3];
        row[0] = up ? *(const float4*)(base - WW) : Z;
        row[1] = *(const float4*)base;
        row[2] = dn ? *(const float4*)(base + WW) : Z;

        #pragma unroll
        for (int ky = 0; ky < 3; ++ky) {
            const float4 V = row[ky];
            float L = __shfl_up_sync(~0u, V.w, 1);   if (g == 0)  L = 0.f;
            float R = __shfl_down_sync(~0u, V.x, 1); if (g == 31) R = 0.f;
            const float k0 = kk[ci * 9 + ky * 3 + 0];
            const float k1 = kk[ci * 9 + ky * 3 + 1];
            const float k2 = kk[ci * 9 + ky * 3 + 2];
            acc.x += k0 * L   + k1 * V.x + k2 * V.y;
            acc.y += k0 * V.x + k1 * V.y + k2 * V.z;
            acc.z += k0 * V.y + k1 * V.z + k2 * V.w;
            acc.w += k0 * V.z + k1 * V.w + k2 * R;
        }
    }
    *(float4*)&d_sphi_part[chunk * HW + r * WW + 4 * g] = acc;
}

// ---------------------------------------------------------------------------
// C: e = exp(sum of 32 chunk partials), float4; per-block S partials. 16x256.
// ---------------------------------------------------------------------------
__global__ void kC() {
    __shared__ float red[8];
    const int t = threadIdx.x;
    const int i4 = blockIdx.x * 256 + t;
    float4 s = make_float4(0.f, 0.f, 0.f, 0.f);
    #pragma unroll
    for (int p = 0; p < 32; ++p) {
        const float4 v = ((const float4*)(d_sphi_part + p * HW))[i4];
        s.x += v.x; s.y += v.y; s.z += v.z; s.w += v.w;
    }
    float4 e = make_float4(__expf(s.x), __expf(s.y), __expf(s.z), __expf(s.w));
    ((float4*)d_e)[i4] = e;
    float v = e.x + e.y + e.z + e.w;
    #pragma unroll
    for (int o = 16; o; o >>= 1) v += __shfl_xor_sync(~0u, v, o);
    if ((t & 31) == 0) red[t >> 5] = v;
    __syncthreads();
    if (t == 0) {
        float tot = 0.f;
        #pragma unroll
        for (int i = 0; i < 8; ++i) tot += red[i];
        d_Spart[blockIdx.x] = tot;
    }
}

// ---------------------------------------------------------------------------
// D: q partials. grid (16 strips of 8 rows, 32 channel-octets) x 256.
// Warp w owns channel oct*8+w over the 8-row strip. Vectorized e-tile fill,
// y preloaded in two batches of 4 (MLP=4), e-window slides in registers,
// one 9-value butterfly per warp.
// ---------------------------------------------------------------------------
__global__ void __launch_bounds__(256, 4) kD(const float* __restrict__ y) {
    __shared__ __align__(16) float sm[10 * 132];
    __shared__ float redsm[72];
    const int t = threadIdx.x;
    const int strip = blockIdx.x;   // 0..15
    const int oct   = blockIdx.y;   // 0..31
    const int h0 = strip * 8;

    // vectorized fill: tile row rr = global e-row h0-1+rr, data at col+1
    #pragma unroll
    for (int i = t; i < 320; i += 256) {
        const int rr = i >> 5, gg = i & 31;
        const int gr = h0 - 1 + rr;
        float4 v = make_float4(0.f, 0.f, 0.f, 0.f);
        if (gr >= 0 && gr < H) v = *(const float4*)(d_e + gr * WW + 4 * gg);
        float* dst = &sm[rr * 132 + 1 + 4 * gg];
        dst[0] = v.x; dst[1] = v.y; dst[2] = v.z; dst[3] = v.w;
    }
    if (t < 20) {                     // col pads: e[-1] and e[128]
        const int rr = t >> 1;
        sm[rr * 132 + ((t & 1) ? 129 : 0)] = 0.f;
    }
    __syncthreads();

    const int w = t >> 5, g = t & 31;
    const int cy = oct * 8 + w;
    const float* yb = y + cy * HW + h0 * WW + 4 * g;

    float a[9];
    #pragma unroll
    for (int k = 0; k < 9; ++k) a[k] = 0.f;

    // sliding e-window: W[ww] = tile row (j + ww); ky = 2 - ww
    float4 E0[3]; float2 E1[3];
    #pragma unroll
    for (int j = 0; j < 3; ++j) {
        const float* bp = &sm[j * 132 + 4 * g];
        E0[j] = *(const float4*)bp;
        E1[j] = *(const float2*)(bp + 4);
    }

    #pragma unroll
    for (int j0 = 0; j0 < 8; j0 += 4) {
        float4 yv[4];
        #pragma unroll
        for (int j = 0; j < 4; ++j) yv[j] = *(const float4*)(yb + (j0 + j) * WW);

        #pragma unroll
        for (int j = 0; j < 4; ++j) {
            #pragma unroll
            for (int ww = 0; ww < 3; ++ww) {
                const int ky = 2 - ww;
                a[3*ky+2] += yv[j].x*E0[ww].x + yv[j].y*E0[ww].y + yv[j].z*E0[ww].z + yv[j].w*E0[ww].w;
                a[3*ky+1] += yv[j].x*E0[ww].y + yv[j].y*E0[ww].z + yv[j].z*E0[ww].w + yv[j].w*E1[ww].x;
                a[3*ky+0] += yv[j].x*E0[ww].z + yv[j].y*E0[ww].w + yv[j].z*E1[ww].x + yv[j].w*E1[ww].y;
            }
            if (j0 + j < 7) {
                E0[0] = E0[1]; E1[0] = E1[1];
                E0[1] = E0[2]; E1[1] = E1[2];
                const float* bp = &sm[(j0 + j + 3) * 132 + 4 * g];
                E0[2] = *(const float4*)bp;
                E1[2] = *(const float2*)(bp + 4);
            }
        }
    }

    #pragma unroll
    for (int k = 0; k < 9; ++k)
        #pragma unroll
        for (int o = 16; o; o >>= 1)
            a[k] += __shfl_xor_sync(~0u, a[k], o);

    if (g == 0) {
        #pragma unroll
        for (int k = 0; k < 9; ++k) redsm[w * 9 + k] = a[k];
    }
    __syncthreads();
    if (t < 72) {
        const int ch = t / 9, k = t - ch * 9;
        d_qe_w[strip * KEL + (oct * 8 + ch) * 9 + k] = redsm[t];
    }
}

// ---------------------------------------------------------------------------
// E0: q[j] = sum over 16 strips.  grid 9 x 256.
// ---------------------------------------------------------------------------
__global__ void kE0() {
    const int j = blockIdx.x * 256 + threadIdx.x;
    float s = 0.f;
    #pragma unroll
    for (int sb = 0; sb < 16; ++sb) s += d_qe_w[sb * KEL + j];
    d_q[j] = s;
}

// ---------------------------------------------------------------------------
// E: r[c] = gamma*(g_w[c,:].q / S + g_b[c]).  256 blocks x 256.
// ---------------------------------------------------------------------------
__global__ void kE(const float* __restrict__ g_w,
                   const float* __restrict__ g_b,
                   const float* __restrict__ gamma) {
    __shared__ float red[256];
    const int c = blockIdx.x, t = threadIdx.x;
    const float4* gw4 = (const float4*)(g_w + c * KEL);
    const float4* q4  = (const float4*)d_q;
    float s = 0.f;
    for (int j = t; j < 576; j += 256) {
        const float4 gv = gw4[j];
        const float4 qv = q4[j];
        s += gv.x * qv.x + gv.y * qv.y + gv.z * qv.z + gv.w * qv.w;
    }
    red[t] = s;
    __syncthreads();
    for (int o = 128; o > 0; o >>= 1) {
        if (t < o) red[t] += red[t + o];
        __syncthreads();
    }
    if (t == 0) {
        float S = 0.f;
        #pragma unroll
        for (int i = 0; i < 16; ++i) S += d_Spart[i];
        d_r[c] = gamma[0] * (red[0] / S + g_b[c]);
    }
}

// ---------------------------------------------------------------------------
// F: broadcast r to 1024 rows, float4.  256 x 256.
// ---------------------------------------------------------------------------
__global__ void kF(float* __restrict__ out) {
    const int i = blockIdx.x * 256 + threadIdx.x;
    ((float4*)out)[i] = ((const float4*)d_r)[i & 63];
}

extern "C" void kernel_launch(void* const* d_in, const int* in_sizes, int n_in,
                              void* d_out, int out_size) {
    // order: x, y, g_w, g_b, phi_w, phi_b, theta_w, theta_b, concat_w, gamma
    const float* y        = (const float*)d_in[1];
    const float* g_w      = (const float*)d_in[2];
    const float* g_b      = (const float*)d_in[3];
    const float* phi_w    = (const float*)d_in[4];
    const float* concat_w = (const float*)d_in[8];
    const float* gamma    = (const float*)d_in[9];

    kA<<<dim3(9, 32), 256>>>(phi_w, concat_w);
    kB<<<dim3(16, 32), 256>>>(y);
    kC<<<16, 256>>>();
    kD<<<dim3(16, 32), 256>>>(y);
    kE0<<<9, 256>>>();
    kE<<<256, 256>>>(g_w, g_b, gamma);
    kF<<<256, 256>>>((float*)d_out);
}

// round 8
// speedup vs baseline: 1.1750x; 1.0920x over previous
#include <cuda_runtime.h>

// ---------------------------------------------------------------------------
// RelationOnSpatial, algebraically collapsed:
//   f = softmax(s_theta[:,None]+s_phi[None,:],axis=1) == softmax(s_phi)
//   (theta path dead, all output rows identical; constant bias cancels).
//   z[i,c] = gamma * ( g_w[c,:,:] . q / S + g_b[c] )
//   q[cy,ky,kx] = sum_{h,w} y[cy,h,w] * e[h+1-ky, w+1-kx],  e=exp(s_phi), S=sum e
// ---------------------------------------------------------------------------

#define CY   256
#define H    128
#define WW   128
#define HW   16384
#define KEL  2304            // CY*9

__device__ float d_phi_part[32 * KEL];                // kA partials (32 chunks)
__device__ __align__(16) float d_sphi_part[32 * HW];  // conv partials per chunk
__device__ __align__(16) float d_e[HW];
__device__ float d_Spart[64];
__device__ float d_qe_w[16 * KEL];                    // per-strip q partials
__device__ __align__(16) float d_q[KEL];
__device__ __align__(16) float d_r[256];

// ---------------------------------------------------------------------------
// A: phi_eff partials over 32 chunks of 8 summed channels.  grid (9,32) x 256.
// ---------------------------------------------------------------------------
__global__ void kA(const float* __restrict__ phi_w,
                   const float* __restrict__ concat_w) {
    const int t   = threadIdx.x;
    const int out = blockIdx.x * 256 + t;
    const int p   = blockIdx.y;
    const float* wp = concat_w + 256;
    float s = 0.f;
    #pragma unroll
    for (int c = p * 8; c < p * 8 + 8; ++c)
        s += wp[c] * phi_w[c * KEL + out];
    d_phi_part[p * KEL + out] = s;
}

// ---------------------------------------------------------------------------
// B: 256ch -> 1ch 3x3 conv partials. grid (16 strips, 32 chunks of 8ch) x 256.
// Warp w owns channel chunk*8+w, sliding down the 8-row strip: each y row is
// loaded ONCE (10 loads per warp) and contributes to 3 output rows from
// registers. Cross-channel sum staged via disjoint smem tiles (fixed order).
// ---------------------------------------------------------------------------
__global__ void __launch_bounds__(256) kB(const float* __restrict__ y) {
    __shared__ float kk[72];
    __shared__ __align__(16) float acc_sm[8][8][128];   // [warp][row][col]
    const int t = threadIdx.x;
    const int strip = blockIdx.x, chunk = blockIdx.y;

    if (t < 72) {
        float s = 0.f;
        #pragma unroll
        for (int p = 0; p < 32; ++p) s += d_phi_part[p * KEL + chunk * 72 + t];
        kk[t] = s;
    }
    __syncthreads();

    const int w = t >> 5, g = t & 31;
    const int cy = chunk * 8 + w;
    const int r0 = strip * 8;

    float k9[9];
    #pragma unroll
    for (int k = 0; k < 9; ++k) k9[k] = kk[w * 9 + k];

    float4 acc[8];
    #pragma unroll
    for (int o = 0; o < 8; ++o) acc[o] = make_float4(0.f, 0.f, 0.f, 0.f);

    const float* yb = y + cy * HW + 4 * g;

    // loaded row j covers global row r0-1+j; contributes as tap ky to
    // local output row lo = j - ky.
    #pragma unroll
    for (int j = 0; j < 10; ++j) {
        const int lr = r0 - 1 + j;
        float4 V = make_float4(0.f, 0.f, 0.f, 0.f);
        if (lr >= 0 && lr < H) V = *(const float4*)(yb + lr * WW);
        float L = __shfl_up_sync(~0u, V.w, 1);   if (g == 0)  L = 0.f;
        float R = __shfl_down_sync(~0u, V.x, 1); if (g == 31) R = 0.f;
        #pragma unroll
        for (int ky = 0; ky < 3; ++ky) {
            const int lo = j - ky;
            if (lo >= 0 && lo < 8) {
                const float k0 = k9[ky * 3 + 0];
                const float k1 = k9[ky * 3 + 1];
                const float k2 = k9[ky * 3 + 2];
                acc[lo].x += k0 * L   + k1 * V.x + k2 * V.y;
                acc[lo].y += k0 * V.x + k1 * V.y + k2 * V.z;
                acc[lo].z += k0 * V.y + k1 * V.z + k2 * V.w;
                acc[lo].w += k0 * V.z + k1 * V.w + k2 * R;
            }
        }
    }

    #pragma unroll
    for (int o = 0; o < 8; ++o)
        *(float4*)&acc_sm[w][o][4 * g] = acc[o];
    __syncthreads();

    // warp w now reduces output row w across the 8 channel buffers
    float4 s = make_float4(0.f, 0.f, 0.f, 0.f);
    #pragma unroll
    for (int b = 0; b < 8; ++b) {
        const float4 v = *(const float4*)&acc_sm[b][w][4 * g];
        s.x += v.x; s.y += v.y; s.z += v.z; s.w += v.w;
    }
    *(float4*)&d_sphi_part[chunk * HW + (r0 + w) * WW + 4 * g] = s;
}

// ---------------------------------------------------------------------------
// C: e = exp(sum of 32 chunk partials); per-block S partials. grid 64 x 256.
// ---------------------------------------------------------------------------
__global__ void kC() {
    __shared__ float red[8];
    const int t = threadIdx.x;
    const int idx = blockIdx.x * 256 + t;
    float s = 0.f;
    #pragma unroll
    for (int p = 0; p < 32; ++p) s += d_sphi_part[p * HW + idx];
    float e = __expf(s);
    d_e[idx] = e;
    float v = e;
    #pragma unroll
    for (int o = 16; o; o >>= 1) v += __shfl_xor_sync(~0u, v, o);
    if ((t & 31) == 0) red[t >> 5] = v;
    __syncthreads();
    if (t == 0) {
        float tot = 0.f;
        #pragma unroll
        for (int i = 0; i < 8; ++i) tot += red[i];
        d_Spart[blockIdx.x] = tot;
    }
}

// ---------------------------------------------------------------------------
// D: q partials. grid (16 strips of 8 rows, 32 channel-octets) x 256.
// Warp w owns channel oct*8+w over the 8-row strip. Vectorized e-tile fill,
// y preloaded in two batches of 4 (MLP=4), e-window slides in registers,
// one 9-value butterfly per warp.
// ---------------------------------------------------------------------------
__global__ void __launch_bounds__(256, 4) kD(const float* __restrict__ y) {
    __shared__ __align__(16) float sm[10 * 132];
    __shared__ float redsm[72];
    const int t = threadIdx.x;
    const int strip = blockIdx.x;   // 0..15
    const int oct   = blockIdx.y;   // 0..31
    const int h0 = strip * 8;

    // vectorized fill: tile row rr = global e-row h0-1+rr, data at col+1
    #pragma unroll
    for (int i = t; i < 320; i += 256) {
        const int rr = i >> 5, gg = i & 31;
        const int gr = h0 - 1 + rr;
        float4 v = make_float4(0.f, 0.f, 0.f, 0.f);
        if (gr >= 0 && gr < H) v = *(const float4*)(d_e + gr * WW + 4 * gg);
        float* dst = &sm[rr * 132 + 1 + 4 * gg];
        dst[0] = v.x; dst[1] = v.y; dst[2] = v.z; dst[3] = v.w;
    }
    if (t < 20) {                     // col pads: e[-1] and e[128]
        const int rr = t >> 1;
        sm[rr * 132 + ((t & 1) ? 129 : 0)] = 0.f;
    }
    __syncthreads();

    const int w = t >> 5, g = t & 31;
    const int cy = oct * 8 + w;
    const float* yb = y + cy * HW + h0 * WW + 4 * g;

    float a[9];
    #pragma unroll
    for (int k = 0; k < 9; ++k) a[k] = 0.f;

    // sliding e-window: W[ww] = tile row (j + ww); ky = 2 - ww
    float4 E0[3]; float2 E1[3];
    #pragma unroll
    for (int j = 0; j < 3; ++j) {
        const float* bp = &sm[j * 132 + 4 * g];
        E0[j] = *(const float4*)bp;
        E1[j] = *(const float2*)(bp + 4);
    }

    #pragma unroll
    for (int j0 = 0; j0 < 8; j0 += 4) {
        float4 yv[4];
        #pragma unroll
        for (int j = 0; j < 4; ++j) yv[j] = *(const float4*)(yb + (j0 + j) * WW);

        #pragma unroll
        for (int j = 0; j < 4; ++j) {
            #pragma unroll
            for (int ww = 0; ww < 3; ++ww) {
                const int ky = 2 - ww;
                a[3*ky+2] += yv[j].x*E0[ww].x + yv[j].y*E0[ww].y + yv[j].z*E0[ww].z + yv[j].w*E0[ww].w;
                a[3*ky+1] += yv[j].x*E0[ww].y + yv[j].y*E0[ww].z + yv[j].z*E0[ww].w + yv[j].w*E1[ww].x;
                a[3*ky+0] += yv[j].x*E0[ww].z + yv[j].y*E0[ww].w + yv[j].z*E1[ww].x + yv[j].w*E1[ww].y;
            }
            if (j0 + j < 7) {
                E0[0] = E0[1]; E1[0] = E1[1];
                E0[1] = E0[2]; E1[1] = E1[2];
                const float* bp = &sm[(j0 + j + 3) * 132 + 4 * g];
                E0[2] = *(const float4*)bp;
                E1[2] = *(const float2*)(bp + 4);
            }
        }
    }

    #pragma unroll
    for (int k = 0; k < 9; ++k)
        #pragma unroll
        for (int o = 16; o; o >>= 1)
            a[k] += __shfl_xor_sync(~0u, a[k], o);

    if (g == 0) {
        #pragma unroll
        for (int k = 0; k < 9; ++k) redsm[w * 9 + k] = a[k];
    }
    __syncthreads();
    if (t < 72) {
        const int ch = t / 9, k = t - ch * 9;
        d_qe_w[strip * KEL + (oct * 8 + ch) * 9 + k] = redsm[t];
    }
}

// ---------------------------------------------------------------------------
// E0: q[j] = sum over 16 strips.  grid 9 x 256.
// ---------------------------------------------------------------------------
__global__ void kE0() {
    const int j = blockIdx.x * 256 + threadIdx.x;
    float s = 0.f;
    #pragma unroll
    for (int sb = 0; sb < 16; ++sb) s += d_qe_w[sb * KEL + j];
    d_q[j] = s;
}

// ---------------------------------------------------------------------------
// E: r[c] = gamma*(g_w[c,:].q / S + g_b[c]).  256 blocks x 256.
// ---------------------------------------------------------------------------
__global__ void kE(const float* __restrict__ g_w,
                   const float* __restrict__ g_b,
                   const float* __restrict__ gamma) {
    __shared__ float red[256];
    const int c = blockIdx.x, t = threadIdx.x;
    const float4* gw4 = (const float4*)(g_w + c * KEL);
    const float4* q4  = (const float4*)d_q;
    float s = 0.f;
    for (int j = t; j < 576; j += 256) {
        const float4 gv = gw4[j];
        const float4 qv = q4[j];
        s += gv.x * qv.x + gv.y * qv.y + gv.z * qv.z + gv.w * qv.w;
    }
    red[t] = s;
    __syncthreads();
    for (int o = 128; o > 0; o >>= 1) {
        if (t < o) red[t] += red[t + o];
        __syncthreads();
    }
    if (t == 0) {
        float S = 0.f;
        #pragma unroll
        for (int i = 0; i < 64; ++i) S += d_Spart[i];
        d_r[c] = gamma[0] * (red[0] / S + g_b[c]);
    }
}

// ---------------------------------------------------------------------------
// F: broadcast r to 1024 rows, float4.  256 x 256.
// ---------------------------------------------------------------------------
__global__ void kF(float* __restrict__ out) {
    const int i = blockIdx.x * 256 + threadIdx.x;
    ((float4*)out)[i] = ((const float4*)d_r)[i & 63];
}

extern "C" void kernel_launch(void* const* d_in, const int* in_sizes, int n_in,
                              void* d_out, int out_size) {
    // order: x, y, g_w, g_b, phi_w, phi_b, theta_w, theta_b, concat_w, gamma
    const float* y        = (const float*)d_in[1];
    const float* g_w      = (const float*)d_in[2];
    const float* g_b      = (const float*)d_in[3];
    const float* phi_w    = (const float*)d_in[4];
    const float* concat_w = (const float*)d_in[8];
    const float* gamma    = (const float*)d_in[9];

    kA<<<dim3(9, 32), 256>>>(phi_w, concat_w);
    kB<<<dim3(16, 32), 256>>>(y);
    kC<<<64, 256>>>();
    kD<<<dim3(16, 32), 256>>>(y);
    kE0<<<9, 256>>>();
    kE<<<256, 256>>>(g_w, g_b, gamma);
    kF<<<256, 256>>>((float*)d_out);
}